// round 1
// baseline (speedup 1.0000x reference)
#include <cuda_runtime.h>

// Problem constants (fixed by the dataset).
#define T_SEQ   4096
#define D_MODEL 2048
#define N_HEADS 32
#define D_HEAD  64
#define BATCH   2
#define M_ROWS  (BATCH * T_SEQ)   // 8192
#define NBLK    (T_SEQ / 128)     // 32 query blocks per batch

// Scratch (device globals: allocation-free rule).
__device__ float g_Q[M_ROWS * D_MODEL];
__device__ float g_K[M_ROWS * D_MODEL];
__device__ float g_V[M_ROWS * D_MODEL];
__device__ float g_A[M_ROWS * D_MODEL];

// ---------------------------------------------------------------------------
// C[m,n] = sum_k A[m,k] * B[n,k]   (A: MxK row-major, B: NxK row-major)
// 128x128 tile, BK=8, 256 threads, 8x8 per thread.
// ---------------------------------------------------------------------------
__global__ __launch_bounds__(256) void sgemm_nt(const float* __restrict__ A,
                                                const float* __restrict__ B,
                                                float* __restrict__ C,
                                                int M, int N, int K)
{
    __shared__ float As[8][128];
    __shared__ float Bs[8][128];
    const int tid = threadIdx.x;
    const int bm = blockIdx.y * 128;
    const int bn = blockIdx.x * 128;
    const int lrow = tid >> 1;          // 0..127
    const int lk   = (tid & 1) << 2;    // 0 or 4
    const int ty = tid >> 4;            // row group
    const int tx = tid & 15;            // col group

    const float* Ap = A + (size_t)(bm + lrow) * K + lk;
    const float* Bp = B + (size_t)(bn + lrow) * K + lk;

    float acc[8][8];
#pragma unroll
    for (int i = 0; i < 8; i++)
#pragma unroll
        for (int j = 0; j < 8; j++) acc[i][j] = 0.f;

    for (int k0 = 0; k0 < K; k0 += 8) {
        float4 av = *(const float4*)(Ap + k0);
        float4 bv = *(const float4*)(Bp + k0);
        As[lk + 0][lrow] = av.x; As[lk + 1][lrow] = av.y;
        As[lk + 2][lrow] = av.z; As[lk + 3][lrow] = av.w;
        Bs[lk + 0][lrow] = bv.x; Bs[lk + 1][lrow] = bv.y;
        Bs[lk + 2][lrow] = bv.z; Bs[lk + 3][lrow] = bv.w;
        __syncthreads();
#pragma unroll
        for (int kk = 0; kk < 8; kk++) {
            float4 a0 = *(const float4*)&As[kk][ty * 8];
            float4 a1 = *(const float4*)&As[kk][ty * 8 + 4];
            float4 b0 = *(const float4*)&Bs[kk][tx * 8];
            float4 b1 = *(const float4*)&Bs[kk][tx * 8 + 4];
            float a[8] = {a0.x, a0.y, a0.z, a0.w, a1.x, a1.y, a1.z, a1.w};
            float b[8] = {b0.x, b0.y, b0.z, b0.w, b1.x, b1.y, b1.z, b1.w};
#pragma unroll
            for (int i = 0; i < 8; i++)
#pragma unroll
                for (int j = 0; j < 8; j++)
                    acc[i][j] += a[i] * b[j];
        }
        __syncthreads();
    }
#pragma unroll
    for (int i = 0; i < 8; i++) {
        float* Cp = C + (size_t)(bm + ty * 8 + i) * N + bn + tx * 8;
        *(float4*)(Cp)     = make_float4(acc[i][0], acc[i][1], acc[i][2], acc[i][3]);
        *(float4*)(Cp + 4) = make_float4(acc[i][4], acc[i][5], acc[i][6], acc[i][7]);
    }
}

// ---------------------------------------------------------------------------
// Fused sliding-window attention.
// One CTA per (q-block i, head h, batch b). window == block size == 128, so
// each q-block attends key blocks {i-1, i} with band mask:
//   valid(r, cg) = (cg >= r) && (cg <= r+128) && (i > 0 || cg >= 128)
// where r in [0,128) local query row, cg in [0,256) local key col.
// ---------------------------------------------------------------------------
#define LS   132   // padded row length for Qs/Ks/S (floats)
#define VROW 72    // padded row length for V tile (floats)

#define SM_QS 0
#define SM_KV (64 * LS)                 // 8448
#define SM_S  (SM_KV + 128 * VROW)      // KV buf = max(64*132, 128*72) = 9216
#define SM_RS (SM_S + 256 * LS)         // + 33792
#define SM_FLOATS (SM_RS + 128)
#define SM_BYTES  (SM_FLOATS * 4)       // 206336 bytes

__global__ __launch_bounds__(256) void swa_attn(const float* __restrict__ Q,
                                                const float* __restrict__ Kmat,
                                                const float* __restrict__ V,
                                                float* __restrict__ O)
{
    extern __shared__ float sm[];
    float* Qs   = sm + SM_QS;   // [64][LS]   Q transposed: Qs[d][r]
    float* KV   = sm + SM_KV;   // K: [64][LS] (Ks[d][c])  /  V: [128][VROW] (Vs[c][d])
    float* S    = sm + SM_S;    // [256][LS]  scores/probs transposed: S[cg][r]
    float* rsum = sm + SM_RS;   // [128] row sums

    const int tid  = threadIdx.x;
    const int iblk = blockIdx.x;
    const int h    = blockIdx.y;
    const int b    = blockIdx.z;
    const int row0 = b * T_SEQ + iblk * 128;
    const int colh = h * D_HEAD;

    // Load Q tile transposed: Qs[d][r]
    for (int t = tid; t < 128 * 16; t += 256) {
        int r  = t >> 4;
        int d4 = (t & 15) << 2;
        float4 v = *(const float4*)(Q + (size_t)(row0 + r) * D_MODEL + colh + d4);
        Qs[(d4 + 0) * LS + r] = v.x;
        Qs[(d4 + 1) * LS + r] = v.y;
        Qs[(d4 + 2) * LS + r] = v.z;
        Qs[(d4 + 3) * LS + r] = v.w;
    }

    const int tx = tid & 15;   // query-row group (8 rows each) for QK
    const int ty = tid >> 4;   // key-col group (8 cols each) for QK
    const float scale = 0.125f;  // 1/sqrt(64)

    // ---- S = (Q K^T) * scale, masked; two 128-key chunks ----
    for (int ch = 0; ch < 2; ch++) {
        int kb = iblk - 1 + ch;
        __syncthreads();  // Q ready (ch=0) / previous chunk consumers done (ch=1)
        if (kb >= 0) {
            int krow0 = b * T_SEQ + kb * 128;
            for (int t = tid; t < 128 * 16; t += 256) {
                int c  = t >> 4;
                int d4 = (t & 15) << 2;
                float4 v = *(const float4*)(Kmat + (size_t)(krow0 + c) * D_MODEL + colh + d4);
                KV[(d4 + 0) * LS + c] = v.x;
                KV[(d4 + 1) * LS + c] = v.y;
                KV[(d4 + 2) * LS + c] = v.z;
                KV[(d4 + 3) * LS + c] = v.w;
            }
        }
        __syncthreads();
        if (kb >= 0) {
            float acc[8][8];  // [i over r][j over c]
#pragma unroll
            for (int i = 0; i < 8; i++)
#pragma unroll
                for (int j = 0; j < 8; j++) acc[i][j] = 0.f;

            for (int d = 0; d < 64; d++) {
                float4 a0 = *(const float4*)&Qs[d * LS + tx * 8];
                float4 a1 = *(const float4*)&Qs[d * LS + tx * 8 + 4];
                float4 b0 = *(const float4*)&KV[d * LS + ty * 8];
                float4 b1 = *(const float4*)&KV[d * LS + ty * 8 + 4];
                float a[8] = {a0.x, a0.y, a0.z, a0.w, a1.x, a1.y, a1.z, a1.w};
                float bb[8] = {b0.x, b0.y, b0.z, b0.w, b1.x, b1.y, b1.z, b1.w};
#pragma unroll
                for (int i = 0; i < 8; i++)
#pragma unroll
                    for (int j = 0; j < 8; j++)
                        acc[i][j] += a[i] * bb[j];
            }
            // Masked write: S[cg][r] (float4 along r -> conflict-free-ish stores)
#pragma unroll
            for (int j = 0; j < 8; j++) {
                int cg = ch * 128 + ty * 8 + j;
                float vals[8];
#pragma unroll
                for (int i = 0; i < 8; i++) {
                    int r = tx * 8 + i;
                    bool valid = (cg >= r) && (cg <= r + 128) && (iblk > 0 || cg >= 128);
                    vals[i] = valid ? acc[i][j] * scale : -1e30f;
                }
                float* Sp = &S[cg * LS + tx * 8];
                *(float4*)Sp       = make_float4(vals[0], vals[1], vals[2], vals[3]);
                *(float4*)(Sp + 4) = make_float4(vals[4], vals[5], vals[6], vals[7]);
            }
        }
    }
    __syncthreads();

    // ---- Row softmax (unnormalized exp; sums saved for epilogue) ----
    if (tid < 128) {
        int r  = tid;
        int c0 = (iblk == 0) ? 128 : 0;   // chunk 0 absent for first block
        float m = -1e30f;
        for (int c = c0; c < 256; c++) m = fmaxf(m, S[c * LS + r]);
        float ssum = 0.f;
        for (int c = c0; c < 256; c++) {
            float e = __expf(S[c * LS + r] - m);
            ssum += e;
            S[c * LS + r] = e;
        }
        rsum[r] = ssum;
    }
    __syncthreads();

    // ---- O = P V ----
    float acc2[8][4];
#pragma unroll
    for (int i = 0; i < 8; i++)
#pragma unroll
        for (int j = 0; j < 4; j++) acc2[i][j] = 0.f;

    const int ry = tid >> 4;  // row group (8 rows)
    const int cx = tid & 15;  // head-dim group (4 cols)
    for (int ch = 0; ch < 2; ch++) {
        int kb = iblk - 1 + ch;
        if (kb >= 0) {
            int krow0 = b * T_SEQ + kb * 128;
            for (int t = tid; t < 128 * 16; t += 256) {
                int c  = t >> 4;
                int d4 = (t & 15) << 2;
                float4 v = *(const float4*)(V + (size_t)(krow0 + c) * D_MODEL + colh + d4);
                *(float4*)&KV[c * VROW + d4] = v;
            }
        }
        __syncthreads();
        if (kb >= 0) {
            for (int cl = 0; cl < 128; cl++) {
                int cg = ch * 128 + cl;
                float4 a0 = *(const float4*)&S[cg * LS + ry * 8];
                float4 a1 = *(const float4*)&S[cg * LS + ry * 8 + 4];
                float4 bv = *(const float4*)&KV[cl * VROW + cx * 4];
                float a[8] = {a0.x, a0.y, a0.z, a0.w, a1.x, a1.y, a1.z, a1.w};
                float bb[4] = {bv.x, bv.y, bv.z, bv.w};
#pragma unroll
                for (int i = 0; i < 8; i++)
#pragma unroll
                    for (int j = 0; j < 4; j++)
                        acc2[i][j] += a[i] * bb[j];
            }
        }
        __syncthreads();
    }

    // Normalize by row sum and store: O[(b,t),(h*64+d)]
#pragma unroll
    for (int i = 0; i < 8; i++) {
        int r = ry * 8 + i;
        float inv = 1.f / rsum[r];
        float4 o = make_float4(acc2[i][0] * inv, acc2[i][1] * inv,
                               acc2[i][2] * inv, acc2[i][3] * inv);
        *(float4*)(O + (size_t)(row0 + r) * D_MODEL + colh + cx * 4) = o;
    }
}

// ---------------------------------------------------------------------------
extern "C" void kernel_launch(void* const* d_in, const int* in_sizes, int n_in,
                              void* d_out, int out_size)
{
    const float* x  = (const float*)d_in[0];
    const float* Wq = (const float*)d_in[1];
    const float* Wk = (const float*)d_in[2];
    const float* Wv = (const float*)d_in[3];
    const float* Wo = (const float*)d_in[4];

    float *Qp, *Kp, *Vp, *Ap;
    cudaGetSymbolAddress((void**)&Qp, g_Q);
    cudaGetSymbolAddress((void**)&Kp, g_K);
    cudaGetSymbolAddress((void**)&Vp, g_V);
    cudaGetSymbolAddress((void**)&Ap, g_A);

    dim3 ggrid(D_MODEL / 128, M_ROWS / 128);  // (16, 64)
    sgemm_nt<<<ggrid, 256>>>(x, Wq, Qp, M_ROWS, D_MODEL, D_MODEL);
    sgemm_nt<<<ggrid, 256>>>(x, Wk, Kp, M_ROWS, D_MODEL, D_MODEL);
    sgemm_nt<<<ggrid, 256>>>(x, Wv, Vp, M_ROWS, D_MODEL, D_MODEL);

    cudaFuncSetAttribute(swa_attn, cudaFuncAttributeMaxDynamicSharedMemorySize, SM_BYTES);
    swa_attn<<<dim3(NBLK, N_HEADS, BATCH), 256, SM_BYTES>>>(Qp, Kp, Vp, Ap);

    sgemm_nt<<<ggrid, 256>>>(Ap, Wo, (float*)d_out, M_ROWS, D_MODEL, D_MODEL);
}

// round 4
// speedup vs baseline: 3.8950x; 3.8950x over previous
#include <cuda_runtime.h>
#include <cstdint>

// Problem constants.
#define T_SEQ   4096
#define D_MODEL 2048
#define N_HEADS 32
#define D_HEAD  64
#define BATCH   2
#define M_ROWS  (BATCH * T_SEQ)   // 8192
#define NBLK    (T_SEQ / 128)     // 32

// Scratch (device globals: allocation-free rule).
__device__ float g_Q [M_ROWS * D_MODEL];
__device__ float g_K [M_ROWS * D_MODEL];
__device__ float g_V [M_ROWS * D_MODEL];
__device__ float g_A [M_ROWS * D_MODEL];
__device__ float g_Xr[M_ROWS * D_MODEL];
__device__ float g_Wq[D_MODEL * D_MODEL];
__device__ float g_Wk[D_MODEL * D_MODEL];
__device__ float g_Wv[D_MODEL * D_MODEL];
__device__ float g_Wo[D_MODEL * D_MODEL];

// ---------------------------------------------------------------------------
// Helpers
// ---------------------------------------------------------------------------
__device__ __forceinline__ uint32_t smem_u32(const void* p) {
    uint32_t a;
    asm("{ .reg .u64 t; cvta.to.shared.u64 t, %1; cvt.u32.u64 %0, t; }" : "=r"(a) : "l"(p));
    return a;
}
__device__ __forceinline__ void cp16(uint32_t s, const void* g) {
    asm volatile("cp.async.cg.shared.global [%0], [%1], 16;" :: "r"(s), "l"(g));
}
__device__ __forceinline__ float to_tf32(float x) {
    uint32_t u;
    asm("cvt.rna.tf32.f32 %0, %1;" : "=r"(u) : "f"(x));
    return __uint_as_float(u);
}
#define SW128(b) ((b) ^ (((b) >> 3) & 0x70))

__device__ __forceinline__ void ldsm4(uint32_t& a, uint32_t& b, uint32_t& c,
                                      uint32_t& d, uint32_t addr) {
    asm volatile("ldmatrix.sync.aligned.m8n8.x4.shared.b16 {%0,%1,%2,%3}, [%4];"
                 : "=r"(a), "=r"(b), "=r"(c), "=r"(d) : "r"(addr));
}
__device__ __forceinline__ void mma8(float* c, const uint32_t* a, const uint32_t* b) {
    asm volatile("mma.sync.aligned.m16n8k8.row.col.f32.tf32.tf32.f32 "
                 "{%0,%1,%2,%3},{%4,%5,%6,%7},{%8,%9},{%0,%1,%2,%3};"
                 : "+f"(c[0]), "+f"(c[1]), "+f"(c[2]), "+f"(c[3])
                 : "r"(a[0]), "r"(a[1]), "r"(a[2]), "r"(a[3]),
                   "r"(b[0]), "r"(b[1]));
}

// ---------------------------------------------------------------------------
// tf32 rounding prep
// ---------------------------------------------------------------------------
__global__ void round_tf32_kernel(const float4* __restrict__ src,
                                  float4* __restrict__ dst, int n4) {
    int i = blockIdx.x * blockDim.x + threadIdx.x;
    if (i < n4) {
        float4 v = src[i];
        v.x = to_tf32(v.x); v.y = to_tf32(v.y);
        v.z = to_tf32(v.z); v.w = to_tf32(v.w);
        dst[i] = v;
    }
}

// ---------------------------------------------------------------------------
// C[m,n] = sum_k A[m,k]*B[n,k]  (A MxK, B NxK row-major, tf32-prerounded).
// mma.sync m16n8k8 tf32. Tile 128x128, BK=32, 8 warps (2x4), warp tile 64x32,
// 3-stage cp.async pipeline, SW128-swizzled k-major smem tiles + ldmatrix.
// ---------------------------------------------------------------------------
#define BK 32
#define STAGE_BYTES 32768              // A 16KB + B 16KB
#define GEMM_SMEM (3 * STAGE_BYTES)    // 98304

__device__ __forceinline__ void gemm_load_chunk(uint32_t smb, int kc,
                                                const float* ag, const float* bg,
                                                uint32_t soff) {
    uint32_t ab = smb + (uint32_t)(kc % 3) * STAGE_BYTES;
    uint32_t bb = ab + 16384;
    const float* agp = ag + kc * BK;
    const float* bgp = bg + kc * BK;
#pragma unroll
    for (int i = 0; i < 4; i++) {
        cp16(ab + soff + i * 4096, agp + (size_t)i * 32 * D_MODEL);
        cp16(bb + soff + i * 4096, bgp + (size_t)i * 32 * D_MODEL);
    }
    asm volatile("cp.async.commit_group;" ::: "memory");
}

__global__ __launch_bounds__(256, 2) void gemm_tf32(const float* __restrict__ A,
                                                    const float* __restrict__ B,
                                                    float* __restrict__ C) {
    extern __shared__ __align__(1024) char sm[];
    uint32_t smb = smem_u32(sm);
    const int tid = threadIdx.x;
    const int wid = tid >> 5, lane = tid & 31;
    const int wm = wid & 1;        // warp M index (0..1), 64 rows each
    const int wn = wid >> 1;       // warp N index (0..3), 32 cols each
    const int bm = blockIdx.y * 128, bn = blockIdx.x * 128;

    // Loader assignment: 4 A rows + 4 B rows (one float4 each) per chunk.
    const int r0 = tid >> 3;       // 0..31
    const int c4 = tid & 7;        // float4 col
    const float* ag = A + (size_t)(bm + r0) * D_MODEL + c4 * 4;
    const float* bg = B + (size_t)(bn + r0) * D_MODEL + c4 * 4;
    const uint32_t soff = SW128((uint32_t)(r0 * 128 + c4 * 16));

    // ldmatrix per-thread source coordinates.
    const int lg = lane >> 3, lr = lane & 7;
    const int a_row = (lg & 1) * 8 + lr;
    const int a_k16 = (lg >> 1) * 16;
    const int b_row = (lg >> 1) * 8 + lr;
    const int b_k16 = (lg & 1) * 16;

    float  Cacc[4][4][4];
    uint32_t Af[4][4], Bf[4][2];
#pragma unroll
    for (int i = 0; i < 4; i++)
#pragma unroll
        for (int j = 0; j < 4; j++)
#pragma unroll
            for (int q = 0; q < 4; q++) Cacc[i][j][q] = 0.f;

    gemm_load_chunk(smb, 0, ag, bg, soff);
    gemm_load_chunk(smb, 1, ag, bg, soff);

    const int NCHUNK = D_MODEL / BK;  // 64
    for (int c = 0; c < NCHUNK; c++) {
        if (c == NCHUNK - 1)
            asm volatile("cp.async.wait_group 0;" ::: "memory");
        else
            asm volatile("cp.async.wait_group 1;" ::: "memory");
        __syncthreads();
        if (c + 2 < NCHUNK) gemm_load_chunk(smb, c + 2, ag, bg, soff);

        uint32_t sa = smb + (uint32_t)(c % 3) * STAGE_BYTES;
        uint32_t sb = sa + 16384;
#pragma unroll
        for (int ks = 0; ks < 4; ks++) {
            const int kb = ks * 32;
#pragma unroll
            for (int ma = 0; ma < 4; ma++) {
                int row = wm * 64 + ma * 16 + a_row;
                uint32_t off = (uint32_t)(row * 128 + ((row & 7) * 16 ^ (kb + a_k16)));
                ldsm4(Af[ma][0], Af[ma][1], Af[ma][2], Af[ma][3], sa + off);
            }
#pragma unroll
            for (int p = 0; p < 2; p++) {
                int n = wn * 32 + p * 16 + b_row;
                uint32_t off = (uint32_t)(n * 128 + ((n & 7) * 16 ^ (kb + b_k16)));
                ldsm4(Bf[p * 2][0], Bf[p * 2][1], Bf[p * 2 + 1][0], Bf[p * 2 + 1][1],
                      sb + off);
            }
#pragma unroll
            for (int ma = 0; ma < 4; ma++)
#pragma unroll
                for (int na = 0; na < 4; na++)
                    mma8(Cacc[ma][na], Af[ma], Bf[na]);
        }
        __syncthreads();
    }

    // Epilogue: c0,c1 -> (row, col..col+1); c2,c3 -> (row+8, ..).
    const int er = lane >> 2, ec = (lane & 3) * 2;
#pragma unroll
    for (int ma = 0; ma < 4; ma++) {
        int grow = bm + wm * 64 + ma * 16 + er;
#pragma unroll
        for (int na = 0; na < 4; na++) {
            int gcol = bn + wn * 32 + na * 8 + ec;
            float* cp0 = C + (size_t)grow * D_MODEL + gcol;
            float* cp1 = C + (size_t)(grow + 8) * D_MODEL + gcol;
            *(float2*)cp0 = make_float2(Cacc[ma][na][0], Cacc[ma][na][1]);
            *(float2*)cp1 = make_float2(Cacc[ma][na][2], Cacc[ma][na][3]);
        }
    }
}

// ---------------------------------------------------------------------------
// Fused sliding-window attention (fp32 SIMT), output rounded to tf32.
// ---------------------------------------------------------------------------
#define LS   132
#define VROW 72
#define SM_QS 0
#define SM_KV (64 * LS)
#define SM_S  (SM_KV + 128 * VROW)
#define SM_RS (SM_S + 256 * LS)
#define SM_FLOATS (SM_RS + 128)
#define SM_BYTES  (SM_FLOATS * 4)

__global__ __launch_bounds__(256) void swa_attn(const float* __restrict__ Q,
                                                const float* __restrict__ Kmat,
                                                const float* __restrict__ V,
                                                float* __restrict__ O) {
    extern __shared__ float smf[];
    float* Qs   = smf + SM_QS;
    float* KV   = smf + SM_KV;
    float* S    = smf + SM_S;
    float* rsum = smf + SM_RS;

    const int tid  = threadIdx.x;
    const int iblk = blockIdx.x;
    const int h    = blockIdx.y;
    const int b    = blockIdx.z;
    const int row0 = b * T_SEQ + iblk * 128;
    const int colh = h * D_HEAD;

    for (int t = tid; t < 128 * 16; t += 256) {
        int r  = t >> 4;
        int d4 = (t & 15) << 2;
        float4 v = *(const float4*)(Q + (size_t)(row0 + r) * D_MODEL + colh + d4);
        Qs[(d4 + 0) * LS + r] = v.x;
        Qs[(d4 + 1) * LS + r] = v.y;
        Qs[(d4 + 2) * LS + r] = v.z;
        Qs[(d4 + 3) * LS + r] = v.w;
    }

    const int tx = tid & 15;
    const int ty = tid >> 4;
    const float scale = 0.125f;

    for (int ch = 0; ch < 2; ch++) {
        int kb = iblk - 1 + ch;
        __syncthreads();
        if (kb >= 0) {
            int krow0 = b * T_SEQ + kb * 128;
            for (int t = tid; t < 128 * 16; t += 256) {
                int c  = t >> 4;
                int d4 = (t & 15) << 2;
                float4 v = *(const float4*)(Kmat + (size_t)(krow0 + c) * D_MODEL + colh + d4);
                KV[(d4 + 0) * LS + c] = v.x;
                KV[(d4 + 1) * LS + c] = v.y;
                KV[(d4 + 2) * LS + c] = v.z;
                KV[(d4 + 3) * LS + c] = v.w;
            }
        }
        __syncthreads();
        if (kb >= 0) {
            float acc[8][8];
#pragma unroll
            for (int i = 0; i < 8; i++)
#pragma unroll
                for (int j = 0; j < 8; j++) acc[i][j] = 0.f;
            for (int d = 0; d < 64; d++) {
                float4 a0 = *(const float4*)&Qs[d * LS + tx * 8];
                float4 a1 = *(const float4*)&Qs[d * LS + tx * 8 + 4];
                float4 b0 = *(const float4*)&KV[d * LS + ty * 8];
                float4 b1 = *(const float4*)&KV[d * LS + ty * 8 + 4];
                float a[8] = {a0.x, a0.y, a0.z, a0.w, a1.x, a1.y, a1.z, a1.w};
                float bb[8] = {b0.x, b0.y, b0.z, b0.w, b1.x, b1.y, b1.z, b1.w};
#pragma unroll
                for (int i = 0; i < 8; i++)
#pragma unroll
                    for (int j = 0; j < 8; j++)
                        acc[i][j] += a[i] * bb[j];
            }
#pragma unroll
            for (int j = 0; j < 8; j++) {
                int cg = ch * 128 + ty * 8 + j;
                float vals[8];
#pragma unroll
                for (int i = 0; i < 8; i++) {
                    int r = tx * 8 + i;
                    bool valid = (cg >= r) && (cg <= r + 128) && (iblk > 0 || cg >= 128);
                    vals[i] = valid ? acc[i][j] * scale : -1e30f;
                }
                float* Sp = &S[cg * LS + tx * 8];
                *(float4*)Sp       = make_float4(vals[0], vals[1], vals[2], vals[3]);
                *(float4*)(Sp + 4) = make_float4(vals[4], vals[5], vals[6], vals[7]);
            }
        }
    }
    __syncthreads();

    if (tid < 128) {
        int r  = tid;
        int c0 = (iblk == 0) ? 128 : 0;
        float m = -1e30f;
        for (int c = c0; c < 256; c++) m = fmaxf(m, S[c * LS + r]);
        float ssum = 0.f;
        for (int c = c0; c < 256; c++) {
            float e = __expf(S[c * LS + r] - m);
            ssum += e;
            S[c * LS + r] = e;
        }
        rsum[r] = ssum;
    }
    __syncthreads();

    float acc2[8][4];
#pragma unroll
    for (int i = 0; i < 8; i++)
#pragma unroll
        for (int j = 0; j < 4; j++) acc2[i][j] = 0.f;

    const int ry = tid >> 4;
    const int cx = tid & 15;
    for (int ch = 0; ch < 2; ch++) {
        int kb = iblk - 1 + ch;
        if (kb >= 0) {
            int krow0 = b * T_SEQ + kb * 128;
            for (int t = tid; t < 128 * 16; t += 256) {
                int c  = t >> 4;
                int d4 = (t & 15) << 2;
                float4 v = *(const float4*)(V + (size_t)(krow0 + c) * D_MODEL + colh + d4);
                *(float4*)&KV[c * VROW + d4] = v;
            }
        }
        __syncthreads();
        if (kb >= 0) {
            for (int cl = 0; cl < 128; cl++) {
                int cg = ch * 128 + cl;
                float4 a0 = *(const float4*)&S[cg * LS + ry * 8];
                float4 a1 = *(const float4*)&S[cg * LS + ry * 8 + 4];
                float4 bv = *(const float4*)&KV[cl * VROW + cx * 4];
                float a[8] = {a0.x, a0.y, a0.z, a0.w, a1.x, a1.y, a1.z, a1.w};
                float bb[4] = {bv.x, bv.y, bv.z, bv.w};
#pragma unroll
                for (int i = 0; i < 8; i++)
#pragma unroll
                    for (int j = 0; j < 4; j++)
                        acc2[i][j] += a[i] * bb[j];
            }
        }
        __syncthreads();
    }

#pragma unroll
    for (int i = 0; i < 8; i++) {
        int r = ry * 8 + i;
        float inv = 1.f / rsum[r];
        float4 o = make_float4(to_tf32(acc2[i][0] * inv), to_tf32(acc2[i][1] * inv),
                               to_tf32(acc2[i][2] * inv), to_tf32(acc2[i][3] * inv));
        *(float4*)(O + (size_t)(row0 + r) * D_MODEL + colh + cx * 4) = o;
    }
}

// ---------------------------------------------------------------------------
extern "C" void kernel_launch(void* const* d_in, const int* in_sizes, int n_in,
                              void* d_out, int out_size) {
    const float* x  = (const float*)d_in[0];
    const float* Wq = (const float*)d_in[1];
    const float* Wk = (const float*)d_in[2];
    const float* Wv = (const float*)d_in[3];
    const float* Wo = (const float*)d_in[4];

    float *Qp, *Kp, *Vp, *Ap, *Xr, *Wqr, *Wkr, *Wvr, *Wor;
    cudaGetSymbolAddress((void**)&Qp,  g_Q);
    cudaGetSymbolAddress((void**)&Kp,  g_K);
    cudaGetSymbolAddress((void**)&Vp,  g_V);
    cudaGetSymbolAddress((void**)&Ap,  g_A);
    cudaGetSymbolAddress((void**)&Xr,  g_Xr);
    cudaGetSymbolAddress((void**)&Wqr, g_Wq);
    cudaGetSymbolAddress((void**)&Wkr, g_Wk);
    cudaGetSymbolAddress((void**)&Wvr, g_Wv);
    cudaGetSymbolAddress((void**)&Wor, g_Wo);

    cudaFuncSetAttribute(gemm_tf32, cudaFuncAttributeMaxDynamicSharedMemorySize, GEMM_SMEM);
    cudaFuncSetAttribute(swa_attn, cudaFuncAttributeMaxDynamicSharedMemorySize, SM_BYTES);

    const int nx4 = M_ROWS * D_MODEL / 4;
    const int nw4 = D_MODEL * D_MODEL / 4;
    round_tf32_kernel<<<nx4 / 256, 256>>>((const float4*)x,  (float4*)Xr,  nx4);
    round_tf32_kernel<<<nw4 / 256, 256>>>((const float4*)Wq, (float4*)Wqr, nw4);
    round_tf32_kernel<<<nw4 / 256, 256>>>((const float4*)Wk, (float4*)Wkr, nw4);
    round_tf32_kernel<<<nw4 / 256, 256>>>((const float4*)Wv, (float4*)Wvr, nw4);
    round_tf32_kernel<<<nw4 / 256, 256>>>((const float4*)Wo, (float4*)Wor, nw4);

    dim3 ggrid(D_MODEL / 128, M_ROWS / 128);  // (16, 64)
    gemm_tf32<<<ggrid, 256, GEMM_SMEM>>>(Xr, Wqr, Qp);
    gemm_tf32<<<ggrid, 256, GEMM_SMEM>>>(Xr, Wkr, Kp);
    gemm_tf32<<<ggrid, 256, GEMM_SMEM>>>(Xr, Wvr, Vp);

    swa_attn<<<dim3(NBLK, N_HEADS, BATCH), 256, SM_BYTES>>>(Qp, Kp, Vp, Ap);

    gemm_tf32<<<ggrid, 256, GEMM_SMEM>>>(Ap, Wor, (float*)d_out);
}

// round 9
// speedup vs baseline: 4.9864x; 1.2802x over previous
#include <cuda_runtime.h>
#include <cstdint>

// Problem constants.
#define T_SEQ   4096
#define D_MODEL 2048
#define N_HEADS 32
#define D_HEAD  64
#define BATCH   2
#define M_ROWS  (BATCH * T_SEQ)   // 8192
#define NBLK    (T_SEQ / 128)     // 32

// Scratch (device globals: allocation-free rule).
__device__ float g_Q [M_ROWS * D_MODEL];
__device__ float g_K [M_ROWS * D_MODEL];
__device__ float g_V [M_ROWS * D_MODEL];
__device__ float g_A [M_ROWS * D_MODEL];
__device__ float g_Xr[M_ROWS * D_MODEL];
__device__ float g_Wq[D_MODEL * D_MODEL];
__device__ float g_Wk[D_MODEL * D_MODEL];
__device__ float g_Wv[D_MODEL * D_MODEL];
__device__ float g_Wo[D_MODEL * D_MODEL];

// ---------------------------------------------------------------------------
// Helpers
// ---------------------------------------------------------------------------
__device__ __forceinline__ uint32_t smem_u32(const void* p) {
    uint32_t a;
    asm("{ .reg .u64 t; cvta.to.shared.u64 t, %1; cvt.u32.u64 %0, t; }" : "=r"(a) : "l"(p));
    return a;
}
__device__ __forceinline__ void cp16(uint32_t s, const void* g) {
    asm volatile("cp.async.cg.shared.global [%0], [%1], 16;" :: "r"(s), "l"(g));
}
__device__ __forceinline__ float to_tf32(float x) {
    uint32_t u;
    asm("cvt.rna.tf32.f32 %0, %1;" : "=r"(u) : "f"(x));
    return __uint_as_float(u);
}
#define SW128(b) ((b) ^ (((b) >> 3) & 0x70))

__device__ __forceinline__ void ldsm4(uint32_t& a, uint32_t& b, uint32_t& c,
                                      uint32_t& d, uint32_t addr) {
    asm volatile("ldmatrix.sync.aligned.m8n8.x4.shared.b16 {%0,%1,%2,%3}, [%4];"
                 : "=r"(a), "=r"(b), "=r"(c), "=r"(d) : "r"(addr));
}
__device__ __forceinline__ void mma8(float* c, const uint32_t* a, const uint32_t* b) {
    asm volatile("mma.sync.aligned.m16n8k8.row.col.f32.tf32.tf32.f32 "
                 "{%0,%1,%2,%3},{%4,%5,%6,%7},{%8,%9},{%0,%1,%2,%3};"
                 : "+f"(c[0]), "+f"(c[1]), "+f"(c[2]), "+f"(c[3])
                 : "r"(a[0]), "r"(a[1]), "r"(a[2]), "r"(a[3]),
                   "r"(b[0]), "r"(b[1]));
}

// ---------------------------------------------------------------------------
// tf32 rounding prep
// ---------------------------------------------------------------------------
__global__ void round_tf32_kernel(const float4* __restrict__ src,
                                  float4* __restrict__ dst, int n4) {
    int i = blockIdx.x * blockDim.x + threadIdx.x;
    if (i < n4) {
        float4 v = src[i];
        v.x = to_tf32(v.x); v.y = to_tf32(v.y);
        v.z = to_tf32(v.z); v.w = to_tf32(v.w);
        dst[i] = v;
    }
}

// ---------------------------------------------------------------------------
// C[m,n] = sum_k A[m,k]*B[n,k]  (A MxK, B NxK row-major, tf32-prerounded).
// ---------------------------------------------------------------------------
#define BK 32
#define STAGE_BYTES 32768              // A 16KB + B 16KB
#define GEMM_SMEM (3 * STAGE_BYTES)    // 98304

__device__ __forceinline__ void gemm_load_chunk(uint32_t smb, int kc,
                                                const float* ag, const float* bg,
                                                uint32_t soff) {
    uint32_t ab = smb + (uint32_t)(kc % 3) * STAGE_BYTES;
    uint32_t bb = ab + 16384;
    const float* agp = ag + kc * BK;
    const float* bgp = bg + kc * BK;
#pragma unroll
    for (int i = 0; i < 4; i++) {
        cp16(ab + soff + i * 4096, agp + (size_t)i * 32 * D_MODEL);
        cp16(bb + soff + i * 4096, bgp + (size_t)i * 32 * D_MODEL);
    }
    asm volatile("cp.async.commit_group;" ::: "memory");
}

__global__ __launch_bounds__(256, 2) void gemm_tf32(const float* __restrict__ A,
                                                    const float* __restrict__ B,
                                                    float* __restrict__ C) {
    extern __shared__ __align__(1024) char sm[];
    uint32_t smb = smem_u32(sm);
    const int tid = threadIdx.x;
    const int wid = tid >> 5, lane = tid & 31;
    const int wm = wid & 1;
    const int wn = wid >> 1;
    const int bm = blockIdx.y * 128, bn = blockIdx.x * 128;

    const int r0 = tid >> 3;
    const int c4 = tid & 7;
    const float* ag = A + (size_t)(bm + r0) * D_MODEL + c4 * 4;
    const float* bg = B + (size_t)(bn + r0) * D_MODEL + c4 * 4;
    const uint32_t soff = SW128((uint32_t)(r0 * 128 + c4 * 16));

    const int lg = lane >> 3, lr = lane & 7;
    const int a_row = (lg & 1) * 8 + lr;
    const int a_k16 = (lg >> 1) * 16;
    const int b_row = (lg >> 1) * 8 + lr;
    const int b_k16 = (lg & 1) * 16;

    float  Cacc[4][4][4];
    uint32_t Af[4][4], Bf[4][2];
#pragma unroll
    for (int i = 0; i < 4; i++)
#pragma unroll
        for (int j = 0; j < 4; j++)
#pragma unroll
            for (int q = 0; q < 4; q++) Cacc[i][j][q] = 0.f;

    gemm_load_chunk(smb, 0, ag, bg, soff);
    gemm_load_chunk(smb, 1, ag, bg, soff);

    const int NCHUNK = D_MODEL / BK;  // 64
    for (int c = 0; c < NCHUNK; c++) {
        if (c == NCHUNK - 1)
            asm volatile("cp.async.wait_group 0;" ::: "memory");
        else
            asm volatile("cp.async.wait_group 1;" ::: "memory");
        __syncthreads();
        if (c + 2 < NCHUNK) gemm_load_chunk(smb, c + 2, ag, bg, soff);

        uint32_t sa = smb + (uint32_t)(c % 3) * STAGE_BYTES;
        uint32_t sb = sa + 16384;
#pragma unroll
        for (int ks = 0; ks < 4; ks++) {
            const int kb = ks * 32;
#pragma unroll
            for (int ma = 0; ma < 4; ma++) {
                int row = wm * 64 + ma * 16 + a_row;
                uint32_t off = (uint32_t)(row * 128 + ((row & 7) * 16 ^ (kb + a_k16)));
                ldsm4(Af[ma][0], Af[ma][1], Af[ma][2], Af[ma][3], sa + off);
            }
#pragma unroll
            for (int p = 0; p < 2; p++) {
                int n = wn * 32 + p * 16 + b_row;
                uint32_t off = (uint32_t)(n * 128 + ((n & 7) * 16 ^ (kb + b_k16)));
                ldsm4(Bf[p * 2][0], Bf[p * 2][1], Bf[p * 2 + 1][0], Bf[p * 2 + 1][1],
                      sb + off);
            }
#pragma unroll
            for (int ma = 0; ma < 4; ma++)
#pragma unroll
                for (int na = 0; na < 4; na++)
                    mma8(Cacc[ma][na], Af[ma], Bf[na]);
        }
        // No trailing __syncthreads(): warps reach the next top sync only
        // after their ldsm reads retired; cp.async writes follow that sync.
    }

    const int er = lane >> 2, ec = (lane & 3) * 2;
#pragma unroll
    for (int ma = 0; ma < 4; ma++) {
        int grow = bm + wm * 64 + ma * 16 + er;
#pragma unroll
        for (int na = 0; na < 4; na++) {
            int gcol = bn + wn * 32 + na * 8 + ec;
            float* cp0 = C + (size_t)grow * D_MODEL + gcol;
            float* cp1 = C + (size_t)(grow + 8) * D_MODEL + gcol;
            *(float2*)cp0 = make_float2(Cacc[ma][na][0], Cacc[ma][na][1]);
            *(float2*)cp1 = make_float2(Cacc[ma][na][2], Cacc[ma][na][3]);
        }
    }
}

// ---------------------------------------------------------------------------
// Tensor-core fused sliding-window attention.
// CTA = (q-block, head, batch), 8 warps; warp w owns q rows 16w..16w+15.
// Q staged RAW fp32 (split hi/lo in regs -> 2-pass QK, error ~K-rounding only).
// K, V staged rna-rounded. iblk==0: window row c maps to key row0-128+c,
// clamped to batch base (clamped rows fully masked).
// ---------------------------------------------------------------------------
#define AT_Q 0
#define AT_K 32768
#define AT_V 98304
#define AT_SMEM 163840

__global__ __launch_bounds__(256, 1) void swa_attn_tc(const float* __restrict__ Q,
                                                      const float* __restrict__ Kmat,
                                                      const float* __restrict__ V,
                                                      float* __restrict__ O) {
    extern __shared__ __align__(1024) char sm[];
    uint32_t smb = smem_u32(sm);
    float* smf = (float*)sm;

    const int tid  = threadIdx.x;
    const int wid  = tid >> 5, lane = tid & 31;
    const int iblk = blockIdx.x;
    const int h    = blockIdx.y;
    const int b    = blockIdx.z;
    const int row0 = b * T_SEQ + iblk * 128;
    const int colh = h * D_HEAD;
    const int bbase = b * T_SEQ;

    // ---- Stage Q raw (2 panels, SW128, cp.async) ----
    for (int idx = tid; idx < 128 * 16; idx += 256) {
        int r = idx >> 4, d4 = idx & 15;
        int panel = d4 >> 3, x = (d4 & 7) * 16;
        cp16(smb + AT_Q + panel * 16384 + r * 128 + (x ^ ((r & 7) * 16)),
             Q + (size_t)(row0 + r) * D_MODEL + colh + d4 * 4);
    }
    asm volatile("cp.async.commit_group;" ::: "memory");

    // ---- Stage K window rounded: row c = tid, key = clamp(row0-128+c) ----
    {
        int krow = row0 - 128 + tid;
        if (krow < bbase) krow = bbase;
        const float* kg = Kmat + (size_t)krow * D_MODEL + colh;
        uint32_t kbase = smb + AT_K + tid * 128;
#pragma unroll
        for (int d4 = 0; d4 < 16; d4++) {
            float4 v = *(const float4*)(kg + d4 * 4);
            v.x = to_tf32(v.x); v.y = to_tf32(v.y);
            v.z = to_tf32(v.z); v.w = to_tf32(v.w);
            int panel = d4 >> 3, x = (d4 & 7) * 16;
            *(float4*)(sm + (kbase - smb) + panel * 32768 + (x ^ ((tid & 7) * 16))) = v;
        }
    }
    // ---- Stage V transposed+rounded: Vt[d][key], 8 panels of 64x128B ----
    {
        int krow = row0 - 128 + tid;
        if (krow < bbase) krow = bbase;
        const float* vg = V + (size_t)krow * D_MODEL + colh;
        const int kp = tid >> 5;
        const int kx = (tid & 31) * 4;
        const int vbase = (AT_V >> 2) + kp * 2048;  // float index
#pragma unroll
        for (int d4 = 0; d4 < 16; d4++) {
            float4 v = *(const float4*)(vg + d4 * 4);
            int d = d4 * 4;
            smf[vbase + (d + 0) * 32 + (((uint32_t)kx ^ (((d + 0) & 7) * 16)) >> 2)] = to_tf32(v.x);
            smf[vbase + (d + 1) * 32 + (((uint32_t)kx ^ (((d + 1) & 7) * 16)) >> 2)] = to_tf32(v.y);
            smf[vbase + (d + 2) * 32 + (((uint32_t)kx ^ (((d + 2) & 7) * 16)) >> 2)] = to_tf32(v.z);
            smf[vbase + (d + 3) * 32 + (((uint32_t)kx ^ (((d + 3) & 7) * 16)) >> 2)] = to_tf32(v.w);
        }
    }
    asm volatile("cp.async.wait_group 0;" ::: "memory");
    __syncthreads();

    const int lg = lane >> 3, lr = lane & 7;
    const int a_row = (lg & 1) * 8 + lr;
    const int a_k16 = (lg >> 1) * 16;
    const int b_row = (lg >> 1) * 8 + lr;
    const int b_k16 = (lg & 1) * 16;
    const int q4 = lane & 3;

    // ---- QK^T (2-pass split): P[32 n-atoms][4] over keys 0..255 ----
    float P[32][4];
#pragma unroll
    for (int i = 0; i < 32; i++)
#pragma unroll
        for (int j = 0; j < 4; j++) P[i][j] = 0.f;

    {
        const int arow_g = wid * 16 + a_row;
        uint32_t Ar[4], Ahi[4], Alo[4], B0, B1, B2, B3;
#pragma unroll
        for (int ks = 0; ks < 8; ks++) {
            int kbyte = ks * 32 + a_k16;
            ldsm4(Ar[0], Ar[1], Ar[2], Ar[3],
                  smb + AT_Q + (kbyte >> 7) * 16384 + arow_g * 128 +
                  ((kbyte & 127) ^ ((arow_g & 7) * 16)));
#pragma unroll
            for (int i = 0; i < 4; i++) {
                float x = __uint_as_float(Ar[i]);
                float hi = to_tf32(x);
                Ahi[i] = __float_as_uint(hi);
                Alo[i] = __float_as_uint(to_tf32(x - hi));
            }
            int kbb = ks * 32 + b_k16;
            uint32_t pb = smb + AT_K + (kbb >> 7) * 32768;
            int xb = kbb & 127;
#pragma unroll
            for (int np = 0; np < 16; np++) {
                int c = np * 16 + b_row;
                ldsm4(B0, B1, B2, B3, pb + c * 128 + (xb ^ ((c & 7) * 16)));
                uint32_t bf0[2] = {B0, B1}, bf1[2] = {B2, B3};
                mma8(P[2 * np], Ahi, bf0);
                mma8(P[2 * np], Alo, bf0);
                mma8(P[2 * np + 1], Ahi, bf1);
                mma8(P[2 * np + 1], Alo, bf1);
            }
        }
    }

    // ---- Mask + softmax (rows r_lo = 16w + lane/4, r_hi = +8) ----
    const int r_lo = wid * 16 + (lane >> 2);
    const int r_hi = r_lo + 8;
    const float scale = 0.125f;
    float m_lo = -1e30f, m_hi = -1e30f;
#pragma unroll
    for (int na = 0; na < 32; na++) {
        int c0 = 8 * na + 2 * q4, c1 = c0 + 1;
        bool ok0 = (iblk > 0 || c0 >= 128);
        bool ok1 = (iblk > 0 || c1 >= 128);
        float s0 = (ok0 && c0 >= r_lo && c0 <= r_lo + 128) ? P[na][0] * scale : -1e30f;
        float s1 = (ok1 && c1 >= r_lo && c1 <= r_lo + 128) ? P[na][1] * scale : -1e30f;
        float s2 = (ok0 && c0 >= r_hi && c0 <= r_hi + 128) ? P[na][2] * scale : -1e30f;
        float s3 = (ok1 && c1 >= r_hi && c1 <= r_hi + 128) ? P[na][3] * scale : -1e30f;
        P[na][0] = s0; P[na][1] = s1; P[na][2] = s2; P[na][3] = s3;
        m_lo = fmaxf(m_lo, fmaxf(s0, s1));
        m_hi = fmaxf(m_hi, fmaxf(s2, s3));
    }
    m_lo = fmaxf(m_lo, __shfl_xor_sync(0xffffffff, m_lo, 1));
    m_lo = fmaxf(m_lo, __shfl_xor_sync(0xffffffff, m_lo, 2));
    m_hi = fmaxf(m_hi, __shfl_xor_sync(0xffffffff, m_hi, 1));
    m_hi = fmaxf(m_hi, __shfl_xor_sync(0xffffffff, m_hi, 2));
    float s_lo = 0.f, s_hi = 0.f;
#pragma unroll
    for (int na = 0; na < 32; na++) {
        float e0 = __expf(P[na][0] - m_lo);
        float e1 = __expf(P[na][1] - m_lo);
        float e2 = __expf(P[na][2] - m_hi);
        float e3 = __expf(P[na][3] - m_hi);
        P[na][0] = e0; P[na][1] = e1; P[na][2] = e2; P[na][3] = e3;
        s_lo += e0 + e1; s_hi += e2 + e3;
    }
    s_lo += __shfl_xor_sync(0xffffffff, s_lo, 1);
    s_lo += __shfl_xor_sync(0xffffffff, s_lo, 2);
    s_hi += __shfl_xor_sync(0xffffffff, s_hi, 1);
    s_hi += __shfl_xor_sync(0xffffffff, s_hi, 2);
    const float inv_lo = 1.f / s_lo, inv_hi = 1.f / s_hi;

    // ---- PV: O8[8 n-atoms][4] over d 0..63, K-dim = keys ----
    float O8[8][4];
#pragma unroll
    for (int i = 0; i < 8; i++)
#pragma unroll
        for (int j = 0; j < 4; j++) O8[i][j] = 0.f;

    const int src1 = (lane & ~3) | (q4 >> 1);
    const int src2 = src1 + 2;
#pragma unroll
    for (int ks = 0; ks < 32; ks++) {
        float u, v, a0f, a1f, a2f, a3f;
        u = __shfl_sync(0xffffffff, P[ks][0], src1);
        v = __shfl_sync(0xffffffff, P[ks][1], src1);
        a0f = (q4 & 1) ? v : u;
        u = __shfl_sync(0xffffffff, P[ks][2], src1);
        v = __shfl_sync(0xffffffff, P[ks][3], src1);
        a1f = (q4 & 1) ? v : u;
        u = __shfl_sync(0xffffffff, P[ks][0], src2);
        v = __shfl_sync(0xffffffff, P[ks][1], src2);
        a2f = (q4 & 1) ? v : u;
        u = __shfl_sync(0xffffffff, P[ks][2], src2);
        v = __shfl_sync(0xffffffff, P[ks][3], src2);
        a3f = (q4 & 1) ? v : u;
        uint32_t Au[4] = {__float_as_uint(to_tf32(a0f)), __float_as_uint(to_tf32(a1f)),
                          __float_as_uint(to_tf32(a2f)), __float_as_uint(to_tf32(a3f))};
        uint32_t vp = smb + AT_V + (ks >> 2) * 8192;
        int kb2 = (ks & 3) * 32 + b_k16;
        uint32_t B0, B1, B2, B3;
#pragma unroll
        for (int p = 0; p < 4; p++) {
            int d = p * 16 + b_row;
            ldsm4(B0, B1, B2, B3, vp + d * 128 + (kb2 ^ ((d & 7) * 16)));
            uint32_t bf0[2] = {B0, B1}, bf1[2] = {B2, B3};
            mma8(O8[2 * p], Au, bf0);
            mma8(O8[2 * p + 1], Au, bf1);
        }
    }

    // ---- Epilogue: normalize, round to tf32 (feeds Wo GEMM), store ----
#pragma unroll
    for (int na = 0; na < 8; na++) {
        int gcol = colh + 8 * na + 2 * q4;
        float* o0 = O + (size_t)(row0 + r_lo) * D_MODEL + gcol;
        float* o1 = O + (size_t)(row0 + r_hi) * D_MODEL + gcol;
        *(float2*)o0 = make_float2(to_tf32(O8[na][0] * inv_lo), to_tf32(O8[na][1] * inv_lo));
        *(float2*)o1 = make_float2(to_tf32(O8[na][2] * inv_hi), to_tf32(O8[na][3] * inv_hi));
    }
}

// ---------------------------------------------------------------------------
extern "C" void kernel_launch(void* const* d_in, const int* in_sizes, int n_in,
                              void* d_out, int out_size) {
    const float* x  = (const float*)d_in[0];
    const float* Wq = (const float*)d_in[1];
    const float* Wk = (const float*)d_in[2];
    const float* Wv = (const float*)d_in[3];
    const float* Wo = (const float*)d_in[4];

    float *Qp, *Kp, *Vp, *Ap, *Xr, *Wqr, *Wkr, *Wvr, *Wor;
    cudaGetSymbolAddress((void**)&Qp,  g_Q);
    cudaGetSymbolAddress((void**)&Kp,  g_K);
    cudaGetSymbolAddress((void**)&Vp,  g_V);
    cudaGetSymbolAddress((void**)&Ap,  g_A);
    cudaGetSymbolAddress((void**)&Xr,  g_Xr);
    cudaGetSymbolAddress((void**)&Wqr, g_Wq);
    cudaGetSymbolAddress((void**)&Wkr, g_Wk);
    cudaGetSymbolAddress((void**)&Wvr, g_Wv);
    cudaGetSymbolAddress((void**)&Wor, g_Wo);

    cudaFuncSetAttribute(gemm_tf32, cudaFuncAttributeMaxDynamicSharedMemorySize, GEMM_SMEM);
    cudaFuncSetAttribute(swa_attn_tc, cudaFuncAttributeMaxDynamicSharedMemorySize, AT_SMEM);

    const int nx4 = M_ROWS * D_MODEL / 4;
    const int nw4 = D_MODEL * D_MODEL / 4;
    round_tf32_kernel<<<nx4 / 256, 256>>>((const float4*)x,  (float4*)Xr,  nx4);
    round_tf32_kernel<<<nw4 / 256, 256>>>((const float4*)Wq, (float4*)Wqr, nw4);
    round_tf32_kernel<<<nw4 / 256, 256>>>((const float4*)Wk, (float4*)Wkr, nw4);
    round_tf32_kernel<<<nw4 / 256, 256>>>((const float4*)Wv, (float4*)Wvr, nw4);
    round_tf32_kernel<<<nw4 / 256, 256>>>((const float4*)Wo, (float4*)Wor, nw4);

    dim3 ggrid(D_MODEL / 128, M_ROWS / 128);  // (16, 64)
    gemm_tf32<<<ggrid, 256, GEMM_SMEM>>>(Xr, Wqr, Qp);
    gemm_tf32<<<ggrid, 256, GEMM_SMEM>>>(Xr, Wkr, Kp);
    gemm_tf32<<<ggrid, 256, GEMM_SMEM>>>(Xr, Wvr, Vp);

    swa_attn_tc<<<dim3(NBLK, N_HEADS, BATCH), 256, AT_SMEM>>>(Qp, Kp, Vp, Ap);

    gemm_tf32<<<ggrid, 256, GEMM_SMEM>>>(Ap, Wor, (float*)d_out);
}